// round 9
// baseline (speedup 1.0000x reference)
#include <cuda_runtime.h>
#include <cuda_bf16.h>
#include <math.h>
#include <stdint.h>

#define N_NODES   100000
#define N_EDGES   1600000
#define IN_FEAT   512
#define HIDDEN    64
#define N_CLASSES 40
#define N_LAYERS  6

#define SCAN_NB   98   // ceil(100000/1024)

// ---------------- device scratch ----------------
__device__ float g_lin[N_NODES * HIDDEN];
__device__ float g_h  [N_NODES * HIDDEN];
__device__ float g_jk [N_NODES * HIDDEN];
__device__ float g_dinv[N_NODES];
__device__ int   g_deg [N_NODES];
__device__ int   g_off [N_NODES + 1];
__device__ int   g_cur [N_NODES];
__device__ int   g_blk [SCAN_NB];
__device__ int   g_blkpref[SCAN_NB];
__device__ int   g_csr_src[N_EDGES];
__device__ float g_csr_w  [N_EDGES];

// packed dual-fp32 FMA (Blackwell f32x2 pipe)
#define FMA_F32X2(d, a, b, c) \
    asm("fma.rn.f32x2 %0, %1, %2, %3;" : "=l"(d) : "l"(a), "l"(b), "l"(c))

// ---------------- degree ----------------
__global__ void k_deg_init() {
    int i = blockIdx.x * blockDim.x + threadIdx.x;
    if (i < N_NODES) g_deg[i] = 1;   // self loop
}

__global__ void k_deg_count(const int* __restrict__ dst) {
    int e = blockIdx.x * blockDim.x + threadIdx.x;
    if (e < N_EDGES) atomicAdd(&g_deg[dst[e]], 1);
}

// ---------------- scan of (deg-1) -> CSR offsets; also computes dinv ------
__global__ void k_scan1() {
    __shared__ int sh[1024];
    int i = blockIdx.x * 1024 + threadIdx.x;
    int deg = (i < N_NODES) ? g_deg[i] : 1;
    if (i < N_NODES) g_dinv[i] = rsqrtf((float)deg);
    int v = (i < N_NODES) ? (deg - 1) : 0;
    sh[threadIdx.x] = v;
    __syncthreads();
#pragma unroll
    for (int o = 1; o < 1024; o <<= 1) {
        int t = (threadIdx.x >= o) ? sh[threadIdx.x - o] : 0;
        __syncthreads();
        sh[threadIdx.x] += t;
        __syncthreads();
    }
    if (i < N_NODES) g_off[i] = sh[threadIdx.x] - v;   // exclusive, intra-block
    if (threadIdx.x == 1023) g_blk[blockIdx.x] = sh[1023];
}

__global__ void k_scan2() {
    __shared__ int sh[SCAN_NB];
    if (threadIdx.x < SCAN_NB) sh[threadIdx.x] = g_blk[threadIdx.x];
    __syncthreads();
    if (threadIdx.x == 0) {
        int run = 0;
        for (int b = 0; b < SCAN_NB; b++) { int t = sh[b]; sh[b] = run; run += t; }
        g_off[N_NODES] = N_EDGES;
    }
    __syncthreads();
    if (threadIdx.x < SCAN_NB) g_blkpref[threadIdx.x] = sh[threadIdx.x];
}

__global__ void k_scan3() {
    int i = blockIdx.x * 1024 + threadIdx.x;
    if (i < N_NODES) {
        int o = g_off[i] + g_blkpref[blockIdx.x];
        g_off[i] = o;
        g_cur[i] = o;
    }
}

__global__ void k_fill(const int* __restrict__ src, const int* __restrict__ dst) {
    int e = blockIdx.x * blockDim.x + threadIdx.x;
    if (e < N_EDGES) {
        int s = src[e], d = dst[e];
        int p = atomicAdd(&g_cur[d], 1);
        g_csr_src[p] = s;
        g_csr_w[p]   = g_dinv[s] * g_dinv[d];
    }
}

// ---------------- GEMM: g_lin[N,64] = A[N,K] @ W[K,64] ----------------
// 64x64 block tile, 128 threads; thread = 4 rows x 8 cols (f32x2 col pairs).
// A kept ROW-major in smem (k contiguous) -> LDS.128 along k, no transpose.
// Inner loop unrolled 4 k-steps: 4 A-LDS.128 + 8 W-LDS.128 + 64 FFMA2.
template <int K, int FROM_H>
__global__ void __launch_bounds__(128)
k_gemm64(const float* __restrict__ A, const float* __restrict__ W) {
    __shared__ __align__(16) float As[64][68];   // [row][k], pitch 68
    __shared__ __align__(16) float Ws[64][64];   // [k][col]

    const float* __restrict__ Asrc = FROM_H ? (const float*)g_h : A;

    const int tx = threadIdx.x & 7;      // col group: cols tx*8 .. tx*8+7
    const int ty = threadIdx.x >> 3;     // row group: rows ty*4 .. ty*4+3 (0..15)
    const int row0 = blockIdx.x * 64;

    unsigned long long acc[4][4];        // [row][col pair]
#pragma unroll
    for (int r = 0; r < 4; r++)
#pragma unroll
        for (int c = 0; c < 4; c++) acc[r][c] = 0ull;

    for (int kc = 0; kc < K; kc += 64) {
        // stage A chunk 64 rows x 64 k (row-major)
#pragma unroll
        for (int i = 0; i < 8; i++) {
            int idx = threadIdx.x + i * 128;
            int r = idx >> 4, c4 = idx & 15;
            int gr = row0 + r;
            float4 v = make_float4(0.f, 0.f, 0.f, 0.f);
            if (gr < N_NODES)
                v = *(const float4*)&Asrc[(size_t)gr * K + kc + c4 * 4];
            *(float4*)&As[r][c4 * 4] = v;
        }
        // stage W chunk 64 k x 64 cols
#pragma unroll
        for (int i = 0; i < 8; i++) {
            int idx = threadIdx.x + i * 128;
            int r = idx >> 4, c4 = idx & 15;
            *(float4*)&Ws[r][c4 * 4] =
                *(const float4*)&W[(size_t)(kc + r) * 64 + c4 * 4];
        }
        __syncthreads();

#pragma unroll 4
        for (int kk = 0; kk < 64; kk += 4) {
            // A: 4 rows x 4 ks
            float4 a4[4];
#pragma unroll
            for (int r = 0; r < 4; r++)
                a4[r] = *(const float4*)&As[ty * 4 + r][kk];
            // W: 4 ks x 8 cols (as 2 u64 pairs per float4)
            ulonglong2 w0[4], w1[4];
#pragma unroll
            for (int j = 0; j < 4; j++) {
                w0[j] = *(const ulonglong2*)&Ws[kk + j][tx * 8];
                w1[j] = *(const ulonglong2*)&Ws[kk + j][tx * 8 + 4];
            }
#pragma unroll
            for (int j = 0; j < 4; j++) {
#pragma unroll
                for (int r = 0; r < 4; r++) {
                    float av = (j == 0) ? a4[r].x : (j == 1) ? a4[r].y
                              : (j == 2) ? a4[r].z : a4[r].w;
                    unsigned int au = __float_as_uint(av);
                    unsigned long long ap;
                    asm("mov.b64 %0, {%1, %1};" : "=l"(ap) : "r"(au));
                    FMA_F32X2(acc[r][0], ap, w0[j].x, acc[r][0]);
                    FMA_F32X2(acc[r][1], ap, w0[j].y, acc[r][1]);
                    FMA_F32X2(acc[r][2], ap, w1[j].x, acc[r][2]);
                    FMA_F32X2(acc[r][3], ap, w1[j].y, acc[r][3]);
                }
            }
        }
        __syncthreads();
    }

#pragma unroll
    for (int r = 0; r < 4; r++) {
        int gr = row0 + ty * 4 + r;
        if (gr < N_NODES) {
            unsigned int lo[4], hi[4];
#pragma unroll
            for (int c = 0; c < 4; c++)
                asm("mov.b64 {%0, %1}, %2;" : "=r"(lo[c]), "=r"(hi[c]) : "l"(acc[r][c]));
            float4 o0 = make_float4(__uint_as_float(lo[0]), __uint_as_float(hi[0]),
                                    __uint_as_float(lo[1]), __uint_as_float(hi[1]));
            float4 o1 = make_float4(__uint_as_float(lo[2]), __uint_as_float(hi[2]),
                                    __uint_as_float(lo[3]), __uint_as_float(hi[3]));
            *(float4*)&g_lin[(size_t)gr * 64 + tx * 8]     = o0;
            *(float4*)&g_lin[(size_t)gr * 64 + tx * 8 + 4] = o1;
        }
    }
}

// ---------------- fused aggregation: selfloop + CSR gather + bias/relu/jk ----
template <int FIRST, int LAST>
__global__ void k_gather(const float* __restrict__ b) {
    unsigned gw   = (blockIdx.x * blockDim.x + threadIdx.x) >> 5;
    unsigned lane = threadIdx.x & 31;
    if (gw >= N_NODES) return;

    const float2* __restrict__ lin2 = (const float2*)g_lin;
    float dn = g_dinv[gw];
    float2 self = lin2[gw * 32u + lane];
    float2 acc = make_float2(dn * dn * self.x, dn * dn * self.y);

    int j = g_off[gw], end = g_off[gw + 1];
    for (; j + 4 <= end; j += 4) {
        int   s0 = g_csr_src[j],     s1 = g_csr_src[j + 1];
        int   s2 = g_csr_src[j + 2], s3 = g_csr_src[j + 3];
        float w0 = g_csr_w[j],       w1 = g_csr_w[j + 1];
        float w2 = g_csr_w[j + 2],   w3 = g_csr_w[j + 3];
        float2 m0 = lin2[(unsigned)s0 * 32u + lane];
        float2 m1 = lin2[(unsigned)s1 * 32u + lane];
        float2 m2 = lin2[(unsigned)s2 * 32u + lane];
        float2 m3 = lin2[(unsigned)s3 * 32u + lane];
        acc.x = fmaf(w0, m0.x, fmaf(w1, m1.x, fmaf(w2, m2.x, fmaf(w3, m3.x, acc.x))));
        acc.y = fmaf(w0, m0.y, fmaf(w1, m1.y, fmaf(w2, m2.y, fmaf(w3, m3.y, acc.y))));
    }
    for (; j < end; j++) {
        int s = g_csr_src[j];
        float w = g_csr_w[j];
        float2 m = lin2[(unsigned)s * 32u + lane];
        acc.x = fmaf(w, m.x, acc.x);
        acc.y = fmaf(w, m.y, acc.y);
    }

    float vx = fmaxf(acc.x + b[lane * 2],     0.f);
    float vy = fmaxf(acc.y + b[lane * 2 + 1], 0.f);
    if (!LAST)
        ((float2*)g_h)[gw * 32u + lane] = make_float2(vx, vy);
    float2* jk2 = (float2*)g_jk;
    if (FIRST) {
        jk2[gw * 32u + lane] = make_float2(vx, vy);
    } else {
        float2 o = jk2[gw * 32u + lane];
        jk2[gw * 32u + lane] = make_float2(fmaxf(o.x, vx), fmaxf(o.y, vy));
    }
}

// ---------------- final: logits = jk @ fcW + fcb; log_softmax ----------------
// 256 threads; block processes 16 nodes (4 passes of 4) reusing Wf in smem.
__global__ void k_final(const float* __restrict__ fcW,
                        const float* __restrict__ fcb,
                        float* __restrict__ out) {
    __shared__ float Wf[HIDDEN * N_CLASSES];
    __shared__ float row[4][HIDDEN];
    __shared__ float logits[4][N_CLASSES];
    __shared__ float lse[4];

    for (int i = threadIdx.x; i < HIDDEN * N_CLASSES; i += 256)
        Wf[i] = fcW[i];

    const int g = threadIdx.x >> 6;
    const int f = threadIdx.x & 63;

    for (int pass = 0; pass < 4; pass++) {
        const int node = blockIdx.x * 16 + pass * 4 + g;
        __syncthreads();

        if (node < N_NODES)
            row[g][f] = g_jk[(size_t)node * HIDDEN + f];
        __syncthreads();

        if (node < N_NODES && f < N_CLASSES) {
            float acc = fcb[f];
#pragma unroll
            for (int h = 0; h < HIDDEN; h++)
                acc = fmaf(row[g][h], Wf[h * N_CLASSES + f], acc);
            logits[g][f] = acc;
        }
        __syncthreads();

        if (node < N_NODES && f == 0) {
            float m = -INFINITY;
#pragma unroll
            for (int c = 0; c < N_CLASSES; c++) m = fmaxf(m, logits[g][c]);
            float s = 0.f;
#pragma unroll
            for (int c = 0; c < N_CLASSES; c++) s += expf(logits[g][c] - m);
            lse[g] = m + logf(s);
        }
        __syncthreads();

        if (node < N_NODES && f < N_CLASSES)
            out[(size_t)node * N_CLASSES + f] = logits[g][f] - lse[g];
    }
}

// ---------------- launch ----------------
extern "C" void kernel_launch(void* const* d_in, const int* in_sizes, int n_in,
                              void* d_out, int out_size) {
    const float* x      = (const float*)d_in[0];
    const int*   edge   = (const int*)d_in[1];     // int64 lowered to int32
    const float* W0     = (const float*)d_in[2];
    const float* b0     = (const float*)d_in[3];
    const float* W_rest = (const float*)d_in[4];
    const float* b_rest = (const float*)d_in[5];
    const float* fcW    = (const float*)d_in[6];
    const float* fcb    = (const float*)d_in[7];
    float* out = (float*)d_out;

    const int* src = edge;
    const int* dst = edge + N_EDGES;

    const int EB = (N_EDGES + 255) / 256;          // 6250
    const int NB = (N_NODES + 255) / 256;
    const int GB = (N_NODES + 63) / 64;            // 1563
    const int AB = (N_NODES * 32 + 255) / 256;     // 12500 (warp per node)

    // launch index 3 gets profiled by ncu -> big GEMM stays there.
    k_deg_init <<<NB, 256>>>();                         // 0
    k_deg_count<<<EB, 256>>>(dst);                      // 1
    k_scan1    <<<SCAN_NB, 1024>>>();                   // 2 (also dinv)
    k_gemm64<IN_FEAT, 0><<<GB, 128>>>(x, W0);           // 3  <- profiled
    k_scan2    <<<1, 128>>>();                          // 4
    k_scan3    <<<SCAN_NB, 1024>>>();                   // 5
    k_fill     <<<EB, 256>>>(src, dst);                 // 6

    // layer 0 aggregation
    k_gather<1, 0><<<AB, 256>>>(b0);

    // layers 1..5
    for (int l = 0; l < N_LAYERS - 1; l++) {
        k_gemm64<HIDDEN, 1><<<GB, 128>>>(nullptr, W_rest + (size_t)l * HIDDEN * HIDDEN);
        if (l < N_LAYERS - 2)
            k_gather<0, 0><<<AB, 256>>>(b_rest + (size_t)l * HIDDEN);
        else
            k_gather<0, 1><<<AB, 256>>>(b_rest + (size_t)l * HIDDEN);
    }

    // final FC + log_softmax
    k_final<<<(N_NODES + 15) / 16, 256>>>(fcW, fcb, out);
}

// round 10
// speedup vs baseline: 1.2817x; 1.2817x over previous
#include <cuda_runtime.h>
#include <cuda_bf16.h>
#include <math.h>
#include <stdint.h>

#define N_NODES   100000
#define N_EDGES   1600000
#define IN_FEAT   512
#define HIDDEN    64
#define N_CLASSES 40
#define N_LAYERS  6

#define SCAN_NB   98   // ceil(100000/1024)

// ---------------- device scratch ----------------
__device__ float g_lin[N_NODES * HIDDEN];
__device__ float g_h  [N_NODES * HIDDEN];
__device__ float g_jk [N_NODES * HIDDEN];
__device__ float g_dinv[N_NODES];
__device__ int   g_deg [N_NODES];
__device__ int   g_off [N_NODES + 1];
__device__ int   g_cur [N_NODES];
__device__ int   g_blk [SCAN_NB];
__device__ int   g_blkpref[SCAN_NB];
__device__ int   g_csr_src[N_EDGES];
__device__ float g_csr_w  [N_EDGES];

// ---------------- degree ----------------
__global__ void k_deg_init() {
    int i = blockIdx.x * blockDim.x + threadIdx.x;
    if (i < N_NODES) g_deg[i] = 1;   // self loop
}

__global__ void k_deg_count(const int* __restrict__ dst) {
    int e = blockIdx.x * blockDim.x + threadIdx.x;
    if (e < N_EDGES) atomicAdd(&g_deg[dst[e]], 1);
}

// ---------------- scan of (deg-1) -> CSR offsets; also computes dinv ------
__global__ void k_scan1() {
    __shared__ int sh[1024];
    int i = blockIdx.x * 1024 + threadIdx.x;
    int deg = (i < N_NODES) ? g_deg[i] : 1;
    if (i < N_NODES) g_dinv[i] = rsqrtf((float)deg);
    int v = (i < N_NODES) ? (deg - 1) : 0;
    sh[threadIdx.x] = v;
    __syncthreads();
#pragma unroll
    for (int o = 1; o < 1024; o <<= 1) {
        int t = (threadIdx.x >= o) ? sh[threadIdx.x - o] : 0;
        __syncthreads();
        sh[threadIdx.x] += t;
        __syncthreads();
    }
    if (i < N_NODES) g_off[i] = sh[threadIdx.x] - v;   // exclusive, intra-block
    if (threadIdx.x == 1023) g_blk[blockIdx.x] = sh[1023];
}

__global__ void k_scan2() {
    __shared__ int sh[SCAN_NB];
    if (threadIdx.x < SCAN_NB) sh[threadIdx.x] = g_blk[threadIdx.x];
    __syncthreads();
    if (threadIdx.x == 0) {
        int run = 0;
        for (int b = 0; b < SCAN_NB; b++) { int t = sh[b]; sh[b] = run; run += t; }
        g_off[N_NODES] = N_EDGES;
    }
    __syncthreads();
    if (threadIdx.x < SCAN_NB) g_blkpref[threadIdx.x] = sh[threadIdx.x];
}

__global__ void k_scan3() {
    int i = blockIdx.x * 1024 + threadIdx.x;
    if (i < N_NODES) {
        int o = g_off[i] + g_blkpref[blockIdx.x];
        g_off[i] = o;
        g_cur[i] = o;
    }
}

__global__ void k_fill(const int* __restrict__ src, const int* __restrict__ dst) {
    int e = blockIdx.x * blockDim.x + threadIdx.x;
    if (e < N_EDGES) {
        int s = src[e], d = dst[e];
        int p = atomicAdd(&g_cur[d], 1);
        g_csr_src[p] = s;
        g_csr_w[p]   = g_dinv[s] * g_dinv[d];
    }
}

// =========== mma.sync tf32x3 GEMM: g_lin[N,64] = A[N,K] @ W[K,64] ===========
// 64x64 block tile, 128 threads (4 warps). Warp computes rows warp*16..+15,
// all 64 cols as 8 m16n8k8 tiles. K staged in chunks of 32 (hi/lo split).
// tf32x3: D += Ahi*Bhi + Alo*Bhi + Ahi*Blo  -> ~2^-22 relative error.

__device__ __forceinline__ void mma_tf32(float d[4],
                                         uint32_t a0, uint32_t a1, uint32_t a2, uint32_t a3,
                                         uint32_t b0, uint32_t b1) {
    asm("mma.sync.aligned.m16n8k8.row.col.f32.tf32.tf32.f32 "
        "{%0,%1,%2,%3}, {%4,%5,%6,%7}, {%8,%9}, {%0,%1,%2,%3};"
        : "+f"(d[0]), "+f"(d[1]), "+f"(d[2]), "+f"(d[3])
        : "r"(a0), "r"(a1), "r"(a2), "r"(a3), "r"(b0), "r"(b1));
}

__device__ __forceinline__ float trunc_hi(float x) {
    return __uint_as_float(__float_as_uint(x) & 0xFFFFE000u);
}

template <int K, int FROM_H>
__global__ void __launch_bounds__(128)
k_gemm_mma(const float* __restrict__ A, const float* __restrict__ W) {
    // pitch 36: frag loads (g*36 + tg) land on distinct banks (4g+tg).
    // pitch 72: frag loads (tg*72 + g) land on distinct banks (8tg+g).
    __shared__ __align__(16) float Ahi[64][36], Alo[64][36];
    __shared__ __align__(16) float Bhi[32][72], Blo[32][72];

    const float* __restrict__ Asrc = FROM_H ? (const float*)g_h : A;

    const int tid  = threadIdx.x;
    const int warp = tid >> 5;
    const int lane = tid & 31;
    const int g    = lane >> 2;      // group id (0..7)
    const int tg   = lane & 3;       // thread in group
    const int row0 = blockIdx.x * 64;

    float d[8][4];
#pragma unroll
    for (int t = 0; t < 8; t++)
#pragma unroll
        for (int c = 0; c < 4; c++) d[t][c] = 0.f;

    for (int kc = 0; kc < K; kc += 32) {
        // ---- stage A chunk: 64 rows x 32 k (hi/lo), float4 quarter-warp-clean ----
#pragma unroll
        for (int i = 0; i < 4; i++) {
            int idx = tid + i * 128;          // 0..511
            int r = idx >> 3, q = idx & 7;
            int gr = row0 + r;
            float4 v = make_float4(0.f, 0.f, 0.f, 0.f);
            if (gr < N_NODES)
                v = *(const float4*)&Asrc[(size_t)gr * K + kc + q * 4];
            float4 h, l;
            h.x = trunc_hi(v.x); l.x = v.x - h.x;
            h.y = trunc_hi(v.y); l.y = v.y - h.y;
            h.z = trunc_hi(v.z); l.z = v.z - h.z;
            h.w = trunc_hi(v.w); l.w = v.w - h.w;
            *(float4*)&Ahi[r][q * 4] = h;
            *(float4*)&Alo[r][q * 4] = l;
        }
        // ---- stage B chunk: 32 k x 64 n (hi/lo) ----
#pragma unroll
        for (int i = 0; i < 4; i++) {
            int idx = tid + i * 128;          // 0..511
            int k = idx >> 4, n4 = idx & 15;
            float4 v = *(const float4*)&W[(size_t)(kc + k) * 64 + n4 * 4];
            float4 h, l;
            h.x = trunc_hi(v.x); l.x = v.x - h.x;
            h.y = trunc_hi(v.y); l.y = v.y - h.y;
            h.z = trunc_hi(v.z); l.z = v.z - h.z;
            h.w = trunc_hi(v.w); l.w = v.w - h.w;
            *(float4*)&Bhi[k][n4 * 4] = h;
            *(float4*)&Blo[k][n4 * 4] = l;
        }
        __syncthreads();

        const int ar0 = warp * 16 + g;
        const int ar1 = ar0 + 8;
#pragma unroll
        for (int k8 = 0; k8 < 32; k8 += 8) {
            // A fragments (m16k8): rows ar0/ar1, cols k8+tg / k8+tg+4
            uint32_t ah0 = __float_as_uint(Ahi[ar0][k8 + tg]);
            uint32_t ah1 = __float_as_uint(Ahi[ar1][k8 + tg]);
            uint32_t ah2 = __float_as_uint(Ahi[ar0][k8 + tg + 4]);
            uint32_t ah3 = __float_as_uint(Ahi[ar1][k8 + tg + 4]);
            uint32_t al0 = __float_as_uint(Alo[ar0][k8 + tg]);
            uint32_t al1 = __float_as_uint(Alo[ar1][k8 + tg]);
            uint32_t al2 = __float_as_uint(Alo[ar0][k8 + tg + 4]);
            uint32_t al3 = __float_as_uint(Alo[ar1][k8 + tg + 4]);
#pragma unroll
            for (int nt = 0; nt < 8; nt++) {
                int bc = nt * 8 + g;          // B col for this lane
                uint32_t bh0 = __float_as_uint(Bhi[k8 + tg][bc]);
                uint32_t bh1 = __float_as_uint(Bhi[k8 + tg + 4][bc]);
                uint32_t bl0 = __float_as_uint(Blo[k8 + tg][bc]);
                uint32_t bl1 = __float_as_uint(Blo[k8 + tg + 4][bc]);
                mma_tf32(d[nt], ah0, ah1, ah2, ah3, bh0, bh1);   // hi*hi
                mma_tf32(d[nt], al0, al1, al2, al3, bh0, bh1);   // lo*hi
                mma_tf32(d[nt], ah0, ah1, ah2, ah3, bl0, bl1);   // hi*lo
            }
        }
        __syncthreads();
    }

    // ---- epilogue: D frag (m16n8): rows g/g+8, cols 2tg, 2tg+1 ----
    const int r0 = row0 + warp * 16 + g;
    const int r1 = r0 + 8;
#pragma unroll
    for (int nt = 0; nt < 8; nt++) {
        int col = nt * 8 + 2 * tg;
        if (r0 < N_NODES)
            *(float2*)&g_lin[(size_t)r0 * 64 + col] = make_float2(d[nt][0], d[nt][1]);
        if (r1 < N_NODES)
            *(float2*)&g_lin[(size_t)r1 * 64 + col] = make_float2(d[nt][2], d[nt][3]);
    }
}

// ---------------- fused aggregation: selfloop + CSR gather + bias/relu/jk ----
template <int FIRST, int LAST>
__global__ void k_gather(const float* __restrict__ b) {
    unsigned gw   = (blockIdx.x * blockDim.x + threadIdx.x) >> 5;
    unsigned lane = threadIdx.x & 31;
    if (gw >= N_NODES) return;

    const float2* __restrict__ lin2 = (const float2*)g_lin;
    float dn = g_dinv[gw];
    float2 self = lin2[gw * 32u + lane];
    float2 acc = make_float2(dn * dn * self.x, dn * dn * self.y);

    int j = g_off[gw], end = g_off[gw + 1];
    for (; j + 4 <= end; j += 4) {
        int   s0 = g_csr_src[j],     s1 = g_csr_src[j + 1];
        int   s2 = g_csr_src[j + 2], s3 = g_csr_src[j + 3];
        float w0 = g_csr_w[j],       w1 = g_csr_w[j + 1];
        float w2 = g_csr_w[j + 2],   w3 = g_csr_w[j + 3];
        float2 m0 = lin2[(unsigned)s0 * 32u + lane];
        float2 m1 = lin2[(unsigned)s1 * 32u + lane];
        float2 m2 = lin2[(unsigned)s2 * 32u + lane];
        float2 m3 = lin2[(unsigned)s3 * 32u + lane];
        acc.x = fmaf(w0, m0.x, fmaf(w1, m1.x, fmaf(w2, m2.x, fmaf(w3, m3.x, acc.x))));
        acc.y = fmaf(w0, m0.y, fmaf(w1, m1.y, fmaf(w2, m2.y, fmaf(w3, m3.y, acc.y))));
    }
    for (; j < end; j++) {
        int s = g_csr_src[j];
        float w = g_csr_w[j];
        float2 m = lin2[(unsigned)s * 32u + lane];
        acc.x = fmaf(w, m.x, acc.x);
        acc.y = fmaf(w, m.y, acc.y);
    }

    float vx = fmaxf(acc.x + b[lane * 2],     0.f);
    float vy = fmaxf(acc.y + b[lane * 2 + 1], 0.f);
    if (!LAST)
        ((float2*)g_h)[gw * 32u + lane] = make_float2(vx, vy);
    float2* jk2 = (float2*)g_jk;
    if (FIRST) {
        jk2[gw * 32u + lane] = make_float2(vx, vy);
    } else {
        float2 o = jk2[gw * 32u + lane];
        jk2[gw * 32u + lane] = make_float2(fmaxf(o.x, vx), fmaxf(o.y, vy));
    }
}

// ---------------- final: logits = jk @ fcW + fcb; log_softmax ----------------
// 256 threads; block processes 16 nodes (4 passes of 4) reusing Wf in smem.
__global__ void k_final(const float* __restrict__ fcW,
                        const float* __restrict__ fcb,
                        float* __restrict__ out) {
    __shared__ float Wf[HIDDEN * N_CLASSES];
    __shared__ float row[4][HIDDEN];
    __shared__ float logits[4][N_CLASSES];
    __shared__ float lse[4];

    for (int i = threadIdx.x; i < HIDDEN * N_CLASSES; i += 256)
        Wf[i] = fcW[i];

    const int g = threadIdx.x >> 6;
    const int f = threadIdx.x & 63;

    for (int pass = 0; pass < 4; pass++) {
        const int node = blockIdx.x * 16 + pass * 4 + g;
        __syncthreads();

        if (node < N_NODES)
            row[g][f] = g_jk[(size_t)node * HIDDEN + f];
        __syncthreads();

        if (node < N_NODES && f < N_CLASSES) {
            float acc = fcb[f];
#pragma unroll
            for (int h = 0; h < HIDDEN; h++)
                acc = fmaf(row[g][h], Wf[h * N_CLASSES + f], acc);
            logits[g][f] = acc;
        }
        __syncthreads();

        if (node < N_NODES && f == 0) {
            float m = -INFINITY;
#pragma unroll
            for (int c = 0; c < N_CLASSES; c++) m = fmaxf(m, logits[g][c]);
            float s = 0.f;
#pragma unroll
            for (int c = 0; c < N_CLASSES; c++) s += expf(logits[g][c] - m);
            lse[g] = m + logf(s);
        }
        __syncthreads();

        if (node < N_NODES && f < N_CLASSES)
            out[(size_t)node * N_CLASSES + f] = logits[g][f] - lse[g];
    }
}

// ---------------- launch ----------------
extern "C" void kernel_launch(void* const* d_in, const int* in_sizes, int n_in,
                              void* d_out, int out_size) {
    const float* x      = (const float*)d_in[0];
    const int*   edge   = (const int*)d_in[1];     // int64 lowered to int32
    const float* W0     = (const float*)d_in[2];
    const float* b0     = (const float*)d_in[3];
    const float* W_rest = (const float*)d_in[4];
    const float* b_rest = (const float*)d_in[5];
    const float* fcW    = (const float*)d_in[6];
    const float* fcb    = (const float*)d_in[7];
    float* out = (float*)d_out;

    const int* src = edge;
    const int* dst = edge + N_EDGES;

    const int EB = (N_EDGES + 255) / 256;          // 6250
    const int NB = (N_NODES + 255) / 256;
    const int GB = (N_NODES + 63) / 64;            // 1563
    const int AB = (N_NODES * 32 + 255) / 256;     // 12500 (warp per node)

    // launch index 3 gets profiled by ncu -> big GEMM stays there.
    k_deg_init <<<NB, 256>>>();                         // 0
    k_deg_count<<<EB, 256>>>(dst);                      // 1
    k_scan1    <<<SCAN_NB, 1024>>>();                   // 2 (also dinv)
    k_gemm_mma<IN_FEAT, 0><<<GB, 128>>>(x, W0);         // 3  <- profiled
    k_scan2    <<<1, 128>>>();                          // 4
    k_scan3    <<<SCAN_NB, 1024>>>();                   // 5
    k_fill     <<<EB, 256>>>(src, dst);                 // 6

    // layer 0 aggregation
    k_gather<1, 0><<<AB, 256>>>(b0);

    // layers 1..5
    for (int l = 0; l < N_LAYERS - 1; l++) {
        k_gemm_mma<HIDDEN, 1><<<GB, 128>>>(nullptr, W_rest + (size_t)l * HIDDEN * HIDDEN);
        if (l < N_LAYERS - 2)
            k_gather<0, 0><<<AB, 256>>>(b_rest + (size_t)l * HIDDEN);
        else
            k_gather<0, 1><<<AB, 256>>>(b_rest + (size_t)l * HIDDEN);
    }

    // final FC + log_softmax
    k_final<<<(N_NODES + 15) / 16, 256>>>(fcW, fcb, out);
}